// round 1
// baseline (speedup 1.0000x reference)
#include <cuda_runtime.h>
#include <cstdint>

#define T_TOT 2048
#define B_TOT 64
#define TNO   501
#define DPI   3.141592653589793

// ---------------- scratch (no allocations allowed) ----------------
__device__ float g_rk[TNO];
__device__ uint2 g_sub[T_TOT];
__device__ float g_th[B_TOT * T_TOT];
__device__ float g_nn[B_TOT * T_TOT];

// ---------------- threefry2x32 (matches jax/_src/prng.py) ----------------
__device__ __forceinline__ uint32_t rotl32(uint32_t x, int r) {
    return (x << r) | (x >> (32 - r));
}

__device__ __forceinline__ void tf2x32(uint32_t k0, uint32_t k1,
                                       uint32_t x0, uint32_t x1,
                                       uint32_t &o0, uint32_t &o1) {
    uint32_t k2 = k0 ^ k1 ^ 0x1BD11BDAu;
    x0 += k0; x1 += k1;
#define TFR(r) { x0 += x1; x1 = rotl32(x1, (r)) ^ x0; }
    TFR(13) TFR(15) TFR(26) TFR(6)
    x0 += k1; x1 += k2 + 1u;
    TFR(17) TFR(29) TFR(16) TFR(24)
    x0 += k2; x1 += k0 + 2u;
    TFR(13) TFR(15) TFR(26) TFR(6)
    x0 += k0; x1 += k1 + 3u;
    TFR(17) TFR(29) TFR(16) TFR(24)
    x0 += k1; x1 += k2 + 4u;
    TFR(13) TFR(15) TFR(26) TFR(6)
    x0 += k2; x1 += k0 + 5u;
#undef TFR
    o0 = x0; o1 = x1;
}

// ---------------- K1: refractory kernel rk = flip(basis.T @ W) ----------------
__global__ void k_rk(const float* __restrict__ W) {
    int t = threadIdx.x;
    if (t >= TNO) return;
    double raw = 7.5 * log(((double)t + 1.0) + 1e-7);
    float acc = 0.f;
    for (int i = 0; i < 30; ++i) {
        double phi = (0.5 * DPI) * (double)i;
        double bv;
        if (raw < phi - DPI || raw > phi + DPI) bv = 0.0;
        else bv = 0.5 * cos(raw - phi) + 0.5;
        acc = fmaf((float)bv, W[i], acc);
    }
    g_rk[500 - t] = acc;   // jnp.flip
}

// ---------------- K2: serial key chain (fold-like split, key(42)=[0,42]) ----------------
__global__ void k_chain() {
    if (threadIdx.x != 0 || blockIdx.x != 0) return;
    uint32_t k0 = 0u, k1 = 42u;
    for (int t = 0; t < T_TOT; ++t) {
        uint32_t a0, a1, b0, b1;
        tf2x32(k0, k1, 0u, 0u, a0, a1);   // next key
        tf2x32(k0, k1, 0u, 1u, b0, b1);   // subkey for this step (independent: ILP 2)
        g_sub[t] = make_uint2(b0, b1);
        k0 = a0; k1 = a1;
    }
}

// ---------------- K3: bernoulli thresholds th[b][t] = logit(u) ----------------
// partitionable 32-bit random_bits: bits = w0 ^ w1 of TF(sub; hi=0, lo=index)
__global__ void k_th() {
    int tid = blockIdx.x * blockDim.x + threadIdx.x;   // b*T + t layout
    int b = tid >> 11;
    int t = tid & (T_TOT - 1);
    uint2 s = g_sub[t];
    uint32_t o0, o1;
    tf2x32(s.x, s.y, 0u, (uint32_t)b, o0, o1);
    uint32_t bits = o0 ^ o1;
    float u = __uint_as_float((bits >> 9) | 0x3f800000u) - 1.0f;
    double ud = (double)u;
    double th = log(ud) - log1p(-ud);   // u==0 -> -inf: spike always (u < P)
    g_th[tid] = (float)th;
}

// ---------------- K4: pointwise tanh-MLP logits ----------------
__global__ void k_nn(const float* __restrict__ V, const float* __restrict__ D,
                     const float* __restrict__ w1, const float* __restrict__ b1,
                     const float* __restrict__ w2, const float* __restrict__ b2) {
    int tid = blockIdx.x * blockDim.x + threadIdx.x;
    float v = V[tid], d = D[tid];
    float acc = 0.f;
    #pragma unroll
    for (int h = 0; h < 5; ++h) {
        float s = fmaf(w1[2 * h + 1], d, w1[2 * h + 0] * v) + b1[h];
        float hh = tanhf(s);
        acc = (h == 0) ? w2[0] * hh : fmaf(w2[h], hh, acc);
    }
    g_nn[tid] = acc + b2[0];
}

// ---------------- K5: autoregressive loop, one warp per batch ----------------
// refract_t = sum_{a=1..501} S[t-a]*rk[501-a]; scatter-forward into contrib[],
// d=1 term (weight rk[500]) carried in a register to shorten the critical path.
__global__ void k_main(float* __restrict__ out) {
    const int b = blockIdx.x;
    const int lane = threadIdx.x;
    __shared__ float contrib[T_TOT + 576];
    __shared__ float nn_sh[T_TOT];
    __shared__ float th_sh[T_TOT];

    for (int i = lane; i < T_TOT + 576; i += 32) contrib[i] = 0.f;
    {
        const float4* nn4 = reinterpret_cast<const float4*>(g_nn + b * T_TOT);
        const float4* th4 = reinterpret_cast<const float4*>(g_th + b * T_TOT);
        float4* nns = reinterpret_cast<float4*>(nn_sh);
        float4* ths = reinterpret_cast<float4*>(th_sh);
        for (int i = lane; i < T_TOT / 4; i += 32) { nns[i] = nn4[i]; ths[i] = th4[i]; }
    }

    float w[16];
    #pragma unroll
    for (int k = 0; k < 16; ++k) {
        int d = lane + 1 + 32 * k;
        w[k] = (d >= 2 && d <= TNO) ? g_rk[TNO - d] : 0.f;
    }
    const float rk500 = g_rk[500];
    __syncwarp();

    float spike = 0.f, c_cur = 0.f;
    float* Sout = out + b * T_TOT;
    float* Pout = out + B_TOT * T_TOT + b * T_TOT;

    for (int t = 0; t < T_TOT; ++t) {
        __syncwarp();                       // make step t-1 scatter visible
        float c_next = contrib[t + 1];      // complete except d=1 (register-carried)
        float x = fmaf(spike, rk500, nn_sh[t] + c_cur);   // logit_t
        float s_new = (x > th_sh[t]) ? 1.f : 0.f;         // == (u < sigmoid(x))
        float P = 1.0f / (1.0f + expf(-x));               // off critical path
        if (lane == 0) { Sout[t] = s_new; Pout[t] = P; }
        if (s_new != 0.f) {                 // warp-uniform branch; spike==1.0 exactly
            #pragma unroll
            for (int k = 0; k < 16; ++k) {
                int d = lane + 1 + 32 * k;
                if (d >= 2 && d <= TNO) contrib[t + d] += w[k];
            }
        }
        spike = s_new;
        c_cur = c_next;
    }
}

// ---------------- launch ----------------
extern "C" void kernel_launch(void* const* d_in, const int* in_sizes, int n_in,
                              void* d_out, int out_size) {
    const float* V  = (const float*)d_in[0];
    const float* D  = (const float*)d_in[1];
    const float* w1 = (const float*)d_in[2];
    const float* b1 = (const float*)d_in[3];
    const float* w2 = (const float*)d_in[4];
    const float* b2 = (const float*)d_in[5];
    const float* Wr = (const float*)d_in[6];
    float* out = (float*)d_out;

    k_rk<<<1, 512>>>(Wr);
    k_chain<<<1, 32>>>();
    k_th<<<(B_TOT * T_TOT) / 256, 256>>>();
    k_nn<<<(B_TOT * T_TOT) / 256, 256>>>(V, D, w1, b1, w2, b2);
    k_main<<<B_TOT, 32>>>(out);
}

// round 2
// speedup vs baseline: 2.6759x; 2.6759x over previous
#include <cuda_runtime.h>
#include <cstdint>
#include <math.h>

#define T_TOT 2048
#define B_TOT 64
#define TNO   501
#define DPI   3.141592653589793
#define EPS_BAND 3e-5f

// ---------------- scratch (no allocations allowed) ----------------
__device__ float g_rk[TNO];
__device__ float g_th[B_TOT * T_TOT];
__device__ float g_u [B_TOT * T_TOT];
__device__ float g_nn[B_TOT * T_TOT];

// ---------------- threefry2x32 (matches jax/_src/prng.py) ----------------
__host__ __device__ __forceinline__ constexpr uint32_t rotl32(uint32_t x, int r) {
    return (x << r) | (x >> (32 - r));
}

struct U2 { uint32_t a, b; };

__host__ __device__ __forceinline__ constexpr U2 tf2x32(uint32_t k0, uint32_t k1,
                                                        uint32_t x0, uint32_t x1) {
    uint32_t k2 = k0 ^ k1 ^ 0x1BD11BDAu;
    x0 += k0; x1 += k1;
#define TFR(r) { x0 += x1; x1 = rotl32(x1, (r)) ^ x0; }
    TFR(13) TFR(15) TFR(26) TFR(6)
    x0 += k1; x1 += k2 + 1u;
    TFR(17) TFR(29) TFR(16) TFR(24)
    x0 += k2; x1 += k0 + 2u;
    TFR(13) TFR(15) TFR(26) TFR(6)
    x0 += k0; x1 += k1 + 3u;
    TFR(17) TFR(29) TFR(16) TFR(24)
    x0 += k1; x1 += k2 + 4u;
    TFR(13) TFR(15) TFR(26) TFR(6)
    x0 += k2; x1 += k0 + 5u;
#undef TFR
    return U2{x0, x1};
}

// ---------------- compile-time key chain: subkeys for all 2048 steps ----------------
// key(42) = [0, 42]; per step (fold-like split, threefry_partitionable):
//   key' = TF(key; 0,0), sub = TF(key; 0,1)
struct SubTab { uint32_t v[2 * T_TOT]; };

constexpr SubTab make_subtab() {
    SubTab s{};
    uint32_t k0 = 0u, k1 = 42u;
    for (int t = 0; t < T_TOT; ++t) {
        U2 nk = tf2x32(k0, k1, 0u, 0u);
        U2 sb = tf2x32(k0, k1, 0u, 1u);
        s.v[2 * t]     = sb.a;
        s.v[2 * t + 1] = sb.b;
        k0 = nk.a; k1 = nk.b;
    }
    return s;
}

__device__ constexpr SubTab g_subtab = make_subtab();

// ---------------- fused precompute: thresholds + uniforms + nn logits + rk ----------------
// blocks 0..511: per-sample u, f32 threshold th=logit(u), nn logit
// blocks 512..513: refractory kernel rk = flip(basis.T @ W)  (identical math to round-1)
__global__ void k_pre(const float* __restrict__ V, const float* __restrict__ D,
                      const float* __restrict__ w1, const float* __restrict__ b1,
                      const float* __restrict__ w2, const float* __restrict__ b2,
                      const float* __restrict__ Wr) {
    if (blockIdx.x >= 512) {
        int t = (blockIdx.x - 512) * 256 + threadIdx.x;
        if (t >= TNO) return;
        double raw = 7.5 * log(((double)t + 1.0) + 1e-7);
        float acc = 0.f;
        for (int i = 0; i < 30; ++i) {
            double phi = (0.5 * DPI) * (double)i;
            double bv;
            if (raw < phi - DPI || raw > phi + DPI) bv = 0.0;
            else bv = 0.5 * cos(raw - phi) + 0.5;
            acc = fmaf((float)bv, Wr[i], acc);
        }
        g_rk[500 - t] = acc;   // jnp.flip
        return;
    }

    int tid = blockIdx.x * 256 + threadIdx.x;   // b*T + t layout
    int b = tid >> 11;
    int t = tid & (T_TOT - 1);

    // bernoulli uniform: partitionable 32-bit random_bits, bits = w0^w1 of TF(sub; 0, b)
    uint32_t s0 = g_subtab.v[2 * t];
    uint32_t s1 = g_subtab.v[2 * t + 1];
    U2 o = tf2x32(s0, s1, 0u, (uint32_t)b);
    uint32_t bits = o.a ^ o.b;
    float u = __uint_as_float((bits >> 9) | 0x3f800000u) - 1.0f;

    // f32 threshold (err <= ~4e-6, far inside EPS_BAND); u==0 -> -inf (always spike)
    float th = logf(u) - log1pf(-u);
    g_th[tid] = th;
    g_u[tid]  = u;

    // pointwise tanh-MLP logits (op-for-op identical to round-1 k_nn)
    float v = V[tid], d = D[tid];
    float acc = 0.f;
    #pragma unroll
    for (int h = 0; h < 5; ++h) {
        float s = fmaf(w1[2 * h + 1], d, w1[2 * h + 0] * v) + b1[h];
        float hh = tanhf(s);
        acc = (h == 0) ? w2[0] * hh : fmaf(w2[h], hh, acc);
    }
    g_nn[tid] = acc + b2[0];
}

// ---------------- autoregressive loop, one warp per batch ----------------
// refract_t = sum_{d=1..501} s_{t-d} * rk[501-d]
// d=1..4 carried in registers (critical path: FFMA->FSETP->SEL), d>=5 scattered
// forward into shared contrib[]; 4 steps of slack -> __syncwarp every 2 steps.
// Sigmoid for P output deferred to a parallel epilogue (off the serial path).
__global__ void k_main(float* __restrict__ out) {
    const int b = blockIdx.x;
    const int lane = threadIdx.x;
    __shared__ float contrib[T_TOT + 528];    // writes up to t+516 (masked w=0 tail)
    __shared__ float nn_sh[T_TOT + 8];
    __shared__ float th_sh[T_TOT];
    __shared__ float x_sh [T_TOT];
    __shared__ float S_sh [T_TOT];

    for (int i = lane; i < T_TOT + 528; i += 32) contrib[i] = 0.f;
    {
        const float4* nn4 = reinterpret_cast<const float4*>(g_nn + b * T_TOT);
        const float4* th4 = reinterpret_cast<const float4*>(g_th + b * T_TOT);
        float4* nns = reinterpret_cast<float4*>(nn_sh);
        float4* ths = reinterpret_cast<float4*>(th_sh);
        for (int i = lane; i < T_TOT / 4; i += 32) { nns[i] = nn4[i]; ths[i] = th4[i]; }
    }
    if (lane < 8) nn_sh[T_TOT + lane] = 0.f;

    // scatter weights: d = 5 + lane + 32k, weight rk[501-d]; masked slots get 0
    float w[16];
    #pragma unroll
    for (int k = 0; k < 16; ++k) {
        int d = 5 + lane + 32 * k;
        w[k] = (d <= TNO) ? g_rk[TNO - d] : 0.f;
    }
    const float W1 = g_rk[500], W2 = g_rk[499], W3 = g_rk[498], W4 = g_rk[497];
    const float* ub = g_u + b * T_TOT;
    __syncwarp();

    float s1 = 0.f, s2 = 0.f, s3 = 0.f, s4 = 0.f;
    float pre = nn_sh[0];     // contrib[0]=0, no prior spikes

#define STEP(t)                                                                 \
    {                                                                           \
        float x  = fmaf(s1, W1, pre);                                           \
        float th = th_sh[t];                                                    \
        float diff = x - th;                                                    \
        float sp = (diff > 0.f) ? 1.f : 0.f;                                    \
        if (fabsf(diff) < EPS_BAND) {  /* rare, warp-uniform: exact fp64 */     \
            double ud = (double)ub[t];                                          \
            double thd = log(ud) - log1p(-ud);                                  \
            sp = ((double)x > thd) ? 1.f : 0.f;                                 \
        }                                                                       \
        x_sh[t] = x;                                                            \
        S_sh[t] = sp;                                                           \
        if (sp != 0.f) {       /* warp-uniform */                               \
            _Pragma("unroll")                                                   \
            for (int k = 0; k < 16; ++k)                                        \
                contrib[(t) + 5 + lane + 32 * k] += w[k];                       \
        }                                                                       \
        s4 = s3; s3 = s2; s2 = s1; s1 = sp;                                     \
        float c = contrib[(t) + 1];                                             \
        pre = fmaf(s2, W2, fmaf(s3, W3, fmaf(s4, W4, nn_sh[(t) + 1] + c)));     \
    }

    for (int t = 0; t < T_TOT; t += 2) {
        STEP(t)
        STEP(t + 1)
        __syncwarp();          // scatter@t visible well before earliest read (t+4)
    }
#undef STEP

    // parallel epilogue: P = sigmoid(x) (same ops as round-1: expf + f32 div)
    float* Sout = out + b * T_TOT;
    float* Pout = out + B_TOT * T_TOT + b * T_TOT;
    for (int i = lane; i < T_TOT; i += 32) {
        float x = x_sh[i];
        Pout[i] = 1.0f / (1.0f + expf(-x));
        Sout[i] = S_sh[i];
    }
}

// ---------------- launch ----------------
extern "C" void kernel_launch(void* const* d_in, const int* in_sizes, int n_in,
                              void* d_out, int out_size) {
    const float* V  = (const float*)d_in[0];
    const float* D  = (const float*)d_in[1];
    const float* w1 = (const float*)d_in[2];
    const float* b1 = (const float*)d_in[3];
    const float* w2 = (const float*)d_in[4];
    const float* b2 = (const float*)d_in[5];
    const float* Wr = (const float*)d_in[6];
    float* out = (float*)d_out;

    k_pre<<<514, 256>>>(V, D, w1, b1, w2, b2, Wr);
    k_main<<<B_TOT, 32>>>(out);
}

// round 6
// speedup vs baseline: 6.3712x; 2.3810x over previous
#include <cuda_runtime.h>
#include <cstdint>
#include <math.h>

#define T_TOT 2048
#define B_TOT 64
#define TNO   501
#define DPI   3.141592653589793

// ---------------- scratch (no allocations allowed) ----------------
__device__ float g_rk[TNO];
__device__ float g_th[B_TOT * T_TOT];
__device__ float g_nn[B_TOT * T_TOT];

// ---------------- threefry2x32 (matches jax/_src/prng.py) ----------------
__host__ __device__ __forceinline__ constexpr uint32_t rotl32(uint32_t x, int r) {
    return (x << r) | (x >> (32 - r));
}

struct U2 { uint32_t a, b; };

__host__ __device__ __forceinline__ constexpr U2 tf2x32(uint32_t k0, uint32_t k1,
                                                        uint32_t x0, uint32_t x1) {
    uint32_t k2 = k0 ^ k1 ^ 0x1BD11BDAu;
    x0 += k0; x1 += k1;
#define TFR(r) { x0 += x1; x1 = rotl32(x1, (r)) ^ x0; }
    TFR(13) TFR(15) TFR(26) TFR(6)
    x0 += k1; x1 += k2 + 1u;
    TFR(17) TFR(29) TFR(16) TFR(24)
    x0 += k2; x1 += k0 + 2u;
    TFR(13) TFR(15) TFR(26) TFR(6)
    x0 += k0; x1 += k1 + 3u;
    TFR(17) TFR(29) TFR(16) TFR(24)
    x0 += k1; x1 += k2 + 4u;
    TFR(13) TFR(15) TFR(26) TFR(6)
    x0 += k2; x1 += k0 + 5u;
#undef TFR
    return U2{x0, x1};
}

// ---------------- compile-time key chain ----------------
struct SubTab { uint32_t v[2 * T_TOT]; };

constexpr SubTab make_subtab() {
    SubTab s{};
    uint32_t k0 = 0u, k1 = 42u;
    for (int t = 0; t < T_TOT; ++t) {
        U2 nk = tf2x32(k0, k1, 0u, 0u);
        U2 sb = tf2x32(k0, k1, 0u, 1u);
        s.v[2 * t]     = sb.a;
        s.v[2 * t + 1] = sb.b;
        k0 = nk.a; k1 = nk.b;
    }
    return s;
}

__device__ constexpr SubTab g_subtab = make_subtab();

// ---------------- double-float log (abs err ~1e-10 over needed range) ----------------
__device__ __forceinline__ void log_df(float v, float& rh, float& rl) {
    int iv = __float_as_int(v);
    int e = ((iv >> 23) & 0xFF) - 127;
    float m = __int_as_float((iv & 0x007FFFFF) | 0x3F800000);
    if (m > 1.4142135f) { m *= 0.5f; e += 1; }
    float num = m - 1.0f;                              // exact (Sterbenz)
    float dh = m + 1.0f;
    float bb = dh - m;
    float dl = (m - (dh - bb)) + (1.0f - bb);
    float q  = num / dh;
    float r  = fmaf(-q, dh, num);
    r        = fmaf(-q, dl, r);
    float zl = r / dh;
    float z2 = q * q;
    float p = 0.0666666667f;
    p = fmaf(p, z2, 0.0769230769f);
    p = fmaf(p, z2, 0.0909090909f);
    p = fmaf(p, z2, 0.1111111111f);
    p = fmaf(p, z2, 0.1428571429f);
    p = fmaf(p, z2, 0.2f);
    p = fmaf(p, z2, 0.3333333333f);
    float hi = 2.0f * q;
    float lo = 2.0f * fmaf(q * z2, p, zl);
    float fe = (float)e;
    float eh = fe * 0.693145751953125f;
    float el = fe * 1.42860682e-06f;
    float s  = eh + hi;
    float b2 = s - eh;
    float er = (hi - b2) + (eh - (s - b2));
    rh = s;
    rl = er + el + lo;
}

__device__ __forceinline__ float floor_f32_of_double(double thd) {
    float T = (float)thd;
    if ((double)T > thd) {
        int ib = __float_as_int(T);
        if (T > 0.f)      ib -= 1;
        else if (T < 0.f) ib += 1;
        else              ib = (int)0x80000001;
        T = __int_as_float(ib);
    }
    return T;
}

// ---------------- fused precompute ----------------
// th[b][t] = floor_f32( logit_fp64(u) ): df fast path + exact-fp64 fallback in
// an ambiguity band. f32 compare (x > th) is then identical to the fp64
// comparison (double)x > logit_fp64(u) for every float x.
__global__ void k_pre(const float* __restrict__ V, const float* __restrict__ D,
                      const float* __restrict__ w1, const float* __restrict__ b1,
                      const float* __restrict__ w2, const float* __restrict__ b2,
                      const float* __restrict__ Wr) {
    if (blockIdx.x >= 512) {
        int t = (blockIdx.x - 512) * 256 + threadIdx.x;
        if (t >= TNO) return;
        double raw = 7.5 * log(((double)t + 1.0) + 1e-7);
        float acc = 0.f;
        for (int i = 0; i < 30; ++i) {
            double phi = (0.5 * DPI) * (double)i;
            double bv;
            if (raw < phi - DPI || raw > phi + DPI) bv = 0.0;
            else bv = 0.5 * cos(raw - phi) + 0.5;
            acc = fmaf((float)bv, Wr[i], acc);
        }
        g_rk[500 - t] = acc;   // jnp.flip
        return;
    }

    int tid = blockIdx.x * 256 + threadIdx.x;   // b*T + t layout
    int b = tid >> 11;
    int t = tid & (T_TOT - 1);

    uint32_t s0 = g_subtab.v[2 * t];
    uint32_t s1 = g_subtab.v[2 * t + 1];
    U2 o = tf2x32(s0, s1, 0u, (uint32_t)b);
    uint32_t bits = o.a ^ o.b;
    uint32_t kb = bits >> 9;                       // u = kb * 2^-23, exact
    float th;
    if (kb == 0u) {
        th = __int_as_float(0xFF800000);           // -inf: always spike
    } else {
        float u = __uint_as_float(kb | 0x3f800000u) - 1.0f;
        float w = 1.0f - u;                        // exact (multiples of 2^-23)
        float luh, lul, lwh, lwl;
        log_df(u, luh, lul);
        log_df(w, lwh, lwl);
        // df subtraction (TwoSum on highs)
        float s  = luh - lwh;
        float bb = s - luh;
        float er = (-lwh - bb) + (luh - (s - bb));
        float lo = er + (lul - lwl);
        float H = s + lo;
        float L = lo - (H - s);
        if (L < 0.0f) {                            // floor: step down one ulp
            int ib = __float_as_int(H);
            if (H > 0.0f)      ib -= 1;
            else if (H < 0.0f) ib += 1;
            else               ib = (int)0x80000001;
            H = __int_as_float(ib);
        }
        // ambiguity check: true thd must lie strictly inside (H, nextup(H))
        float dist = (s - H) + lo;                 // thd - H (df)
        int ih = __float_as_int(H);
        float Hn = __int_as_float((H > 0.f) ? ih + 1 : ((H < 0.f) ? ih - 1 : 1));
        float width = Hn - H;
        float eps = 1e-9f + 2e-9f * fabsf(H);
        if (!(dist > eps && (width - dist) > eps)) {
            double ud = (double)u;
            double thd = log(ud) - log1p(-ud);     // exact fp64 path (rare)
            H = floor_f32_of_double(thd);
        }
        th = H;
    }
    g_th[tid] = th;

    // pointwise tanh-MLP logits (identical math to passing rounds)
    float v = V[tid], d = D[tid];
    float acc = 0.f;
    #pragma unroll
    for (int h = 0; h < 5; ++h) {
        float s = fmaf(w1[2 * h + 1], d, w1[2 * h + 0] * v) + b1[h];
        float hh = tanhf(s);
        acc = (h == 0) ? w2[0] * hh : fmaf(w2[h], hh, acc);
    }
    g_nn[tid] = acc + b2[0];
}

// ---------------- autoregressive loop: 3 warps per batch ----------------
// warp0: serial chain. d=1..4 in registers; d=5..132 via pair-combined scatter
//        (each lane RMWs only addresses j = t+5+lane+32k it exclusively owns
//        within the pair; reuse across pairs is __syncwarp-separated).
// warps 1,2: race-free GATHER of far taps d=133..501: during block bk they
//        compute FarB[j] for j in [64bk+66, 64bk+129] (one owner lane per j),
//        reading spikes that are >= 1 block old (bar.sync-separated).
#define AN_LEN 2208
#define FB_LEN 2176
#define TH_LEN 2056
#define SPAD   512
#define S_LEN  (SPAD + T_TOT)
#define RK_LEN 512

__global__ void __launch_bounds__(96, 1) k_main(float* __restrict__ out) {
    __shared__ float An[AN_LEN];      // init = nn (j<2048) else 0; near accum
    __shared__ float FarB[FB_LEN];
    __shared__ float th_sh[TH_LEN];
    __shared__ float x_sh[T_TOT];
    __shared__ float S_arr[S_LEN];    // 512-zero prefix, then spikes
    __shared__ float rk_sh[RK_LEN];

    const int b = blockIdx.x;
    const int tid = threadIdx.x;
    const int wid = tid >> 5;
    const int lane = tid & 31;

    // ---- init ----
    {
        const float4* nn4 = reinterpret_cast<const float4*>(g_nn + b * T_TOT);
        const float4* th4 = reinterpret_cast<const float4*>(g_th + b * T_TOT);
        float4* An4 = reinterpret_cast<float4*>(An);
        float4* Th4 = reinterpret_cast<float4*>(th_sh);
        for (int i = tid; i < T_TOT / 4; i += 96) { An4[i] = nn4[i]; Th4[i] = th4[i]; }
    }
    for (int i = T_TOT + tid; i < AN_LEN; i += 96) An[i] = 0.f;
    for (int i = T_TOT + tid; i < TH_LEN; i += 96) th_sh[i] = 0.f;
    for (int i = tid; i < FB_LEN; i += 96) FarB[i] = 0.f;
    for (int i = tid; i < SPAD; i += 96) S_arr[i] = 0.f;   // zero prefix only
    for (int i = tid; i < RK_LEN; i += 96) rk_sh[i] = (i < TNO) ? g_rk[i] : 0.f;
    __syncthreads();

    if (wid == 0) {
        // ---- serial warp ----
        const float W1 = rk_sh[500], W2 = rk_sh[499], W3 = rk_sh[498], W4 = rk_sh[497];
        // pair scatter weights: address j = t+5+lane+32k
        //   step t   (sp0): d0 = 5+lane+32k  -> rk[496-lane-32k]
        //   step t+1 (sp1): d1 = 4+lane+32k  -> rk[497-lane-32k]  (d1=4 excluded)
        const float wA0 = rk_sh[496 - lane];
        const float wA1 = rk_sh[464 - lane];
        const float wA2 = rk_sh[432 - lane];
        const float wA3 = rk_sh[400 - lane];
        const float wB0 = (lane == 0) ? 0.f : rk_sh[497 - lane];
        const float wB1 = rk_sh[465 - lane];
        const float wB2 = rk_sh[433 - lane];
        const float wB3 = rk_sh[401 - lane];
        const float wX  = rk_sh[369];          // j = t+133, d1 = 132 (lane 0 only)

        // history registers at pair (t,t+1) entry: s1=s_{t-1}, s2=s_{t-2}, s3=s_{t-3}
        float s1 = 0.f, s2 = 0.f, s3 = 0.f;
        float preA  = An[0] + FarB[0];    // step 0: no prior spikes
        float baseB = An[1] + FarB[1];
        float thA = th_sh[0], thB = th_sh[1];
        int t = 0;

        for (int bk = 0; bk < 32; ++bk) {
            #pragma unroll 2
            for (int i = 0; i < 32; ++i) {
                // step t   (d=1: s_{t-1}=s1; d=2..4 folded into preA last pair)
                float x0  = fmaf(s1, W1, preA);
                float sp0 = (x0 > thA) ? 1.f : 0.f;
                x_sh[t] = x0; S_arr[SPAD + t] = sp0;
                float anC = An[t + 2], fbC = FarB[t + 2];
                thA = th_sh[t + 2];
                // step t+1 (d=1: s_t=sp0; d=2: s_{t-1}=s1; d=3: s2; d=4: s3)
                float preB = fmaf(s1, W2, fmaf(s2, W3, fmaf(s3, W4, baseB)));
                float x1  = fmaf(sp0, W1, preB);
                float sp1 = (x1 > thB) ? 1.f : 0.f;
                x_sh[t + 1] = x1; S_arr[SPAD + t + 1] = sp1;
                float anD = An[t + 3], fbD = FarB[t + 3];
                thB = th_sh[t + 3];
                // pair-combined scatter: lane-owned addresses only
                float* an = An + t + 5 + lane;
                an[0]  += fmaf(sp0, wA0, sp1 * wB0);
                an[32] += fmaf(sp0, wA1, sp1 * wB1);
                an[64] += fmaf(sp0, wA2, sp1 * wB2);
                an[96] += fmaf(sp0, wA3, sp1 * wB3);
                if (lane == 0) an[128] += sp1 * wX;
                // carries for next pair — FIXED register taps:
                // step t+2 needs d=2: s_t=sp0 (W2), d=3: s_{t-1}=s1 (W3), d=4: s_{t-2}=s2 (W4)
                preA  = fmaf(sp0, W2, fmaf(s1, W3, fmaf(s2, W4, anC + fbC)));
                baseB = anD + fbD;
                s3 = s1; s2 = sp0; s1 = sp1;
                t += 2;
                __syncwarp();
            }
            asm volatile("bar.sync 0, 96;" ::: "memory");
        }
    } else {
        // ---- gather warps: far background, race-free single-owner writes ----
        const int j0 = 66 + (wid - 1) * 32 + lane;
        for (int bk = 0; bk < 32; ++bk) {
            int j = 64 * bk + j0;
            const float* sp = S_arr + (SPAD + j - 501);
            float a0 = 0.f, a1 = 0.f, a2 = 0.f;
            #pragma unroll 4
            for (int m = 0; m < 369; m += 3) {
                a0 = fmaf(sp[m],     rk_sh[m],     a0);
                a1 = fmaf(sp[m + 1], rk_sh[m + 1], a1);
                a2 = fmaf(sp[m + 2], rk_sh[m + 2], a2);
            }
            FarB[j] = a0 + a1 + a2;     // single owner write
            asm volatile("bar.sync 0, 96;" ::: "memory");
        }
    }

    // ---- parallel epilogue: P = sigmoid(x) (same ops as passing rounds) ----
    float* Sout = out + b * T_TOT;
    float* Pout = out + B_TOT * T_TOT + b * T_TOT;
    for (int i = tid; i < T_TOT; i += 96) {
        float x = x_sh[i];
        Pout[i] = 1.0f / (1.0f + expf(-x));
        Sout[i] = S_arr[SPAD + i];
    }
}

// ---------------- launch ----------------
extern "C" void kernel_launch(void* const* d_in, const int* in_sizes, int n_in,
                              void* d_out, int out_size) {
    const float* V  = (const float*)d_in[0];
    const float* D  = (const float*)d_in[1];
    const float* w1 = (const float*)d_in[2];
    const float* b1 = (const float*)d_in[3];
    const float* w2 = (const float*)d_in[4];
    const float* b2 = (const float*)d_in[5];
    const float* Wr = (const float*)d_in[6];
    float* out = (float*)d_out;

    k_pre<<<514, 256>>>(V, D, w1, b1, w2, b2, Wr);
    k_main<<<B_TOT, 96>>>(out);
}